// round 7
// baseline (speedup 1.0000x reference)
#include <cuda_runtime.h>
#include <cstdint>

// out[dst] += x[src]. x: [N,64] f32, edge_index: [2,E] int32 on device.
//
// Two-phase, TWO launches:
//   fill:   bin edges by dst into fixed-capacity per-node lists (atomic slot
//           counters in __device__ scratch).
//   gather: node-parallel register accumulation + one plain STG.128 per quad;
//           folds in (never-in-practice) overflow edges; then SELF-CLEANS the
//           scratch counters so no reset launch is needed: __device__ globals
//           are zero-init at load, and every execution restores the all-zero
//           invariant before it ends (q==0 thread zeroes g_cnt[node];
//           last-block ticket zeroes g_of_count).
// Fallback pure-atomic path for N > N_MAX.

#define N_MAX  50000
#define CAP    64
#define MAX_OF 65536

__device__ int g_cnt[N_MAX];                 // zero-init at module load
__device__ int g_lists[N_MAX * CAP];
__device__ int g_of_src[MAX_OF];
__device__ int g_of_dst[MAX_OF];
__device__ int g_of_count;                   // zero-init at module load
__device__ unsigned g_done;                  // zero-init at module load

__device__ __forceinline__ void red_add_v4(float* p, float4 v) {
    asm volatile("red.global.add.v4.f32 [%0], {%1, %2, %3, %4};"
                 :: "l"(p), "f"(v.x), "f"(v.y), "f"(v.z), "f"(v.w)
                 : "memory");
}

__device__ __forceinline__ void acc_add(float4& a, float4 v) {
    a.x += v.x; a.y += v.y; a.z += v.z; a.w += v.w;
}

// ---- phase 1: bin edges by dst (4 edges per thread, int4 index loads) ----
__global__ void mp_fill_kernel(const int* __restrict__ ei, int E) {
    int g = blockIdx.x * blockDim.x + threadIdx.x;
    int e0 = g * 4;
    if (e0 >= E) return;

    int s[4], d[4];
    int m;
    if (e0 + 3 < E) {
        int4 sv = __ldg((const int4*)(ei + e0));
        int4 dv = __ldg((const int4*)(ei + E + e0));
        s[0] = sv.x; s[1] = sv.y; s[2] = sv.z; s[3] = sv.w;
        d[0] = dv.x; d[1] = dv.y; d[2] = dv.z; d[3] = dv.w;
        m = 4;
    } else {
        m = E - e0;
        for (int k = 0; k < m; ++k) {
            s[k] = __ldg(ei + e0 + k);
            d[k] = __ldg(ei + E + e0 + k);
        }
    }

    int p[4];
    #pragma unroll
    for (int k = 0; k < 4; ++k)                 // independent atomic chains
        p[k] = (k < m) ? atomicAdd(&g_cnt[d[k]], 1) : 0;

    #pragma unroll
    for (int k = 0; k < 4; ++k) {
        if (k >= m) break;
        if (p[k] < CAP) {
            g_lists[d[k] * CAP + p[k]] = s[k];
        } else {
            int o = atomicAdd(&g_of_count, 1);
            if (o < MAX_OF) { g_of_src[o] = s[k]; g_of_dst[o] = d[k]; }
        }
    }
}

// ---- phase 2: gather-accumulate (+inline overflow), store, self-clean ----
__global__ void mp_gather_kernel(const float4* __restrict__ x,
                                 float4* __restrict__ out, int N) {
    int idx = blockIdx.x * blockDim.x + threadIdx.x;
    int node = idx >> 4;
    int q    = idx & 15;
    bool valid = (node < N);

    if (valid) {
        int c = g_cnt[node];
        if (q == 0) g_cnt[node] = 0;             // restore zero invariant
        if (c > CAP) c = CAP;
        const int4* lst4 = (const int4*)(g_lists + node * CAP);

        float4 a0 = make_float4(0.f, 0.f, 0.f, 0.f);
        float4 a1 = make_float4(0.f, 0.f, 0.f, 0.f);
        float4 a2 = make_float4(0.f, 0.f, 0.f, 0.f);
        float4 a3 = make_float4(0.f, 0.f, 0.f, 0.f);

        int j = 0;
        for (; j + 3 < c; j += 4) {
            int4 s = __ldg(lst4 + (j >> 2));       // 4 src indices, one LDG
            float4 v0 = __ldg(x + s.x * 16 + q);   // 4 independent chains
            float4 v1 = __ldg(x + s.y * 16 + q);
            float4 v2 = __ldg(x + s.z * 16 + q);
            float4 v3 = __ldg(x + s.w * 16 + q);
            acc_add(a0, v0); acc_add(a1, v1); acc_add(a2, v2); acc_add(a3, v3);
        }
        if (j < c) {
            const int* lst = (const int*)lst4;
            for (; j < c; ++j)
                acc_add(a0, __ldg(x + __ldg(lst + j) * 16 + q));
        }

        // Fold in overflow edges targeting this node (expected: none).
        int nof = g_of_count;
        if (nof > 0) {
            if (nof > MAX_OF) nof = MAX_OF;
            for (int i = 0; i < nof; ++i)
                if (g_of_dst[i] == node)
                    acc_add(a0, __ldg(x + g_of_src[i] * 16 + q));
        }

        acc_add(a0, a1); acc_add(a2, a3); acc_add(a0, a2);
        out[node * 16 + q] = a0;
    }

    // Last-block ticket: zero g_of_count only after ALL blocks finished
    // reading it. Restores the zero invariant for the next execution.
    __syncthreads();
    if (threadIdx.x == 0) {
        unsigned t = atomicAdd(&g_done, 1u);
        if (t == gridDim.x - 1) {
            g_of_count = 0;
            g_done = 0;
        }
    }
}

// ---- fallback (N > N_MAX): pure atomic path ------------------------------
__global__ void mp_zero_kernel(float4* __restrict__ out, int n4) {
    int i = blockIdx.x * blockDim.x + threadIdx.x;
    if (i < n4) out[i] = make_float4(0.f, 0.f, 0.f, 0.f);
}

__global__ void mp_scatter_kernel(const float4* __restrict__ x,
                                  const int* __restrict__ ei,
                                  float* __restrict__ out, int E) {
    int idx = blockIdx.x * blockDim.x + threadIdx.x;
    int e = idx >> 4, q = idx & 15;
    if (e >= E) return;
    int src = __ldg(ei + e);
    int dst = __ldg(ei + E + e);
    float4 v = __ldg(x + src * 16 + q);
    red_add_v4(out + dst * 64 + q * 4, v);
}

extern "C" void kernel_launch(void* const* d_in, const int* in_sizes, int n_in,
                              void* d_out, int out_size) {
    const float4* x = (const float4*)d_in[0];
    const int* ei = (const int*)d_in[1];
    float* out = (float*)d_out;

    int E = in_sizes[1] / 2;          // 800000
    int N = in_sizes[0] / 64;         // 50000

    if (N <= N_MAX) {
        int groups = (E + 3) / 4;
        mp_fill_kernel<<<(groups + 255) / 256, 256>>>(ei, E);
        long long work = (long long)N * 16;
        mp_gather_kernel<<<(int)((work + 255) / 256), 256>>>(x, (float4*)out, N);
    } else {
        int n4 = out_size / 4;
        mp_zero_kernel<<<(n4 + 255) / 256, 256>>>((float4*)out, n4);
        long long work = (long long)E * 16;
        mp_scatter_kernel<<<(int)((work + 255) / 256), 256>>>(x, ei, out, E);
    }
}

// round 8
// speedup vs baseline: 1.2255x; 1.2255x over previous
#include <cuda_runtime.h>
#include <cstdint>

// out[dst] += x[src]. x: [N,64] f32, edge_index: [2,E] int32 on device.
//
// Three launches (small ones pipeline to ~free under graph replay):
//   reset:  zero per-node slot counters + overflow count.
//   fill:   bin edges by dst into fixed-capacity per-node lists.
//   gather: node-parallel register accumulation, software-pipelined index
//           loads (prefetch next int4 of srcs while 4 gathers are in flight),
//           one plain STG.128 per quad. Overflow (prob ~1e-17) folded in
//           before the store. No float atomics in the common path.
// Fallback pure-atomic path for N > N_MAX.

#define N_MAX  50000
#define CAP    64
#define MAX_OF 65536

__device__ int g_cnt[N_MAX];
__device__ int g_lists[N_MAX * CAP];
__device__ int g_of_src[MAX_OF];
__device__ int g_of_dst[MAX_OF];
__device__ int g_of_count;

__device__ __forceinline__ void red_add_v4(float* p, float4 v) {
    asm volatile("red.global.add.v4.f32 [%0], {%1, %2, %3, %4};"
                 :: "l"(p), "f"(v.x), "f"(v.y), "f"(v.z), "f"(v.w)
                 : "memory");
}

__device__ __forceinline__ void acc_add(float4& a, float4 v) {
    a.x += v.x; a.y += v.y; a.z += v.z; a.w += v.w;
}

// ---- phase 0: reset counters --------------------------------------------
__global__ void mp_reset_kernel(int N) {
    int i = blockIdx.x * blockDim.x + threadIdx.x;
    if (i < N) g_cnt[i] = 0;
    if (i == 0) g_of_count = 0;
}

// ---- phase 1: bin edges by dst (4 edges per thread, int4 index loads) ----
__global__ void mp_fill_kernel(const int* __restrict__ ei, int E) {
    int g = blockIdx.x * blockDim.x + threadIdx.x;
    int e0 = g * 4;
    if (e0 >= E) return;

    int s[4], d[4];
    int m;
    if (e0 + 3 < E) {
        int4 sv = __ldg((const int4*)(ei + e0));
        int4 dv = __ldg((const int4*)(ei + E + e0));
        s[0] = sv.x; s[1] = sv.y; s[2] = sv.z; s[3] = sv.w;
        d[0] = dv.x; d[1] = dv.y; d[2] = dv.z; d[3] = dv.w;
        m = 4;
    } else {
        m = E - e0;
        for (int k = 0; k < m; ++k) {
            s[k] = __ldg(ei + e0 + k);
            d[k] = __ldg(ei + E + e0 + k);
        }
    }
    #pragma unroll
    for (int k = 0; k < 4; ++k) {
        if (k >= m) break;
        int p = atomicAdd(&g_cnt[d[k]], 1);
        if (p < CAP) {
            g_lists[d[k] * CAP + p] = s[k];
        } else {
            int o = atomicAdd(&g_of_count, 1);
            if (o < MAX_OF) { g_of_src[o] = s[k]; g_of_dst[o] = d[k]; }
        }
    }
}

// ---- phase 2: gather-accumulate (+inline overflow), plain store ---------
__global__ void mp_gather_kernel(const float4* __restrict__ x,
                                 float4* __restrict__ out, int N) {
    int idx = blockIdx.x * blockDim.x + threadIdx.x;
    int node = idx >> 4;
    int q    = idx & 15;
    if (node >= N) return;

    int c = g_cnt[node];
    if (c > CAP) c = CAP;
    const int4* lst4 = (const int4*)(g_lists + node * CAP);
    int nvec = c >> 2;                       // full int4 groups

    float4 a0 = make_float4(0.f, 0.f, 0.f, 0.f);
    float4 a1 = make_float4(0.f, 0.f, 0.f, 0.f);
    float4 a2 = make_float4(0.f, 0.f, 0.f, 0.f);
    float4 a3 = make_float4(0.f, 0.f, 0.f, 0.f);

    if (nvec > 0) {
        int4 s = __ldg(lst4);                // prime the pipeline
        for (int v = 0; v < nvec; ++v) {
            int4 cur = s;
            if (v + 1 < nvec) s = __ldg(lst4 + v + 1);   // prefetch next
            float4 v0 = __ldg(x + cur.x * 16 + q);       // 4 chains in flight
            float4 v1 = __ldg(x + cur.y * 16 + q);
            float4 v2 = __ldg(x + cur.z * 16 + q);
            float4 v3 = __ldg(x + cur.w * 16 + q);
            acc_add(a0, v0); acc_add(a1, v1); acc_add(a2, v2); acc_add(a3, v3);
        }
    }
    {
        const int* lst = (const int*)lst4;
        for (int j = nvec << 2; j < c; ++j)
            acc_add(a0, __ldg(x + __ldg(lst + j) * 16 + q));
    }

    // Fold in overflow edges targeting this node (expected: none).
    int nof = g_of_count;
    if (nof > 0) {
        if (nof > MAX_OF) nof = MAX_OF;
        for (int i = 0; i < nof; ++i)
            if (g_of_dst[i] == node)
                acc_add(a0, __ldg(x + g_of_src[i] * 16 + q));
    }

    acc_add(a0, a1); acc_add(a2, a3); acc_add(a0, a2);
    out[node * 16 + q] = a0;
}

// ---- fallback (N > N_MAX): pure atomic path ------------------------------
__global__ void mp_zero_kernel(float4* __restrict__ out, int n4) {
    int i = blockIdx.x * blockDim.x + threadIdx.x;
    if (i < n4) out[i] = make_float4(0.f, 0.f, 0.f, 0.f);
}

__global__ void mp_scatter_kernel(const float4* __restrict__ x,
                                  const int* __restrict__ ei,
                                  float* __restrict__ out, int E) {
    int idx = blockIdx.x * blockDim.x + threadIdx.x;
    int e = idx >> 4, q = idx & 15;
    if (e >= E) return;
    int src = __ldg(ei + e);
    int dst = __ldg(ei + E + e);
    float4 v = __ldg(x + src * 16 + q);
    red_add_v4(out + dst * 64 + q * 4, v);
}

extern "C" void kernel_launch(void* const* d_in, const int* in_sizes, int n_in,
                              void* d_out, int out_size) {
    const float4* x = (const float4*)d_in[0];
    const int* ei = (const int*)d_in[1];
    float* out = (float*)d_out;

    int E = in_sizes[1] / 2;          // 800000
    int N = in_sizes[0] / 64;         // 50000

    if (N <= N_MAX) {
        mp_reset_kernel<<<(N + 255) / 256, 256>>>(N);
        int groups = (E + 3) / 4;
        mp_fill_kernel<<<(groups + 255) / 256, 256>>>(ei, E);
        long long work = (long long)N * 16;
        mp_gather_kernel<<<(int)((work + 255) / 256), 256>>>(x, (float4*)out, N);
    } else {
        int n4 = out_size / 4;
        mp_zero_kernel<<<(n4 + 255) / 256, 256>>>((float4*)out, n4);
        long long work = (long long)E * 16;
        mp_scatter_kernel<<<(int)((work + 255) / 256), 256>>>(x, ei, out, E);
    }
}

// round 9
// speedup vs baseline: 1.3313x; 1.0863x over previous
#include <cuda_runtime.h>
#include <cstdint>

// out[dst] += x[src]. x: [N,64] f32, edge_index: [2,E] int32 on device.
//
// Three launches: reset -> fill (bin by dst) -> gather (register accumulate,
// one plain STG.128 per quad; overflow folded in; no float atomics).
// Gather main loop: 8 edges/iter, all loads unconditional and front-batched
// (codegen-sensitive: conditional prefetch regressed in round 8).
// Fallback pure-atomic path for N > N_MAX.

#define N_MAX  50000
#define CAP    64
#define MAX_OF 65536

__device__ int g_cnt[N_MAX];
__device__ int g_lists[N_MAX * CAP];
__device__ int g_of_src[MAX_OF];
__device__ int g_of_dst[MAX_OF];
__device__ int g_of_count;

__device__ __forceinline__ void red_add_v4(float* p, float4 v) {
    asm volatile("red.global.add.v4.f32 [%0], {%1, %2, %3, %4};"
                 :: "l"(p), "f"(v.x), "f"(v.y), "f"(v.z), "f"(v.w)
                 : "memory");
}

__device__ __forceinline__ void acc_add(float4& a, float4 v) {
    a.x += v.x; a.y += v.y; a.z += v.z; a.w += v.w;
}

// ---- phase 0: reset counters (vectorized) --------------------------------
__global__ void mp_reset_kernel(int N) {
    int i = blockIdx.x * blockDim.x + threadIdx.x;
    int n4 = N >> 2;
    if (i < n4) ((int4*)g_cnt)[i] = make_int4(0, 0, 0, 0);
    if (i == n4) {                  // tail (N not divisible by 4) + of_count
        for (int k = n4 << 2; k < N; ++k) g_cnt[k] = 0;
        g_of_count = 0;
    }
}

// ---- phase 1: bin edges by dst (4 edges/thread, hoisted atomics) ---------
__global__ void mp_fill_kernel(const int* __restrict__ ei, int E) {
    int g = blockIdx.x * blockDim.x + threadIdx.x;
    int e0 = g * 4;
    if (e0 >= E) return;

    int s[4], d[4];
    int m;
    if (e0 + 3 < E) {
        int4 sv = __ldg((const int4*)(ei + e0));
        int4 dv = __ldg((const int4*)(ei + E + e0));
        s[0] = sv.x; s[1] = sv.y; s[2] = sv.z; s[3] = sv.w;
        d[0] = dv.x; d[1] = dv.y; d[2] = dv.z; d[3] = dv.w;
        m = 4;
    } else {
        m = E - e0;
        for (int k = 0; k < m; ++k) {
            s[k] = __ldg(ei + e0 + k);
            d[k] = __ldg(ei + E + e0 + k);
        }
    }

    int p[4];
    #pragma unroll
    for (int k = 0; k < 4; ++k)             // 4 independent atomic chains
        p[k] = (k < m) ? atomicAdd(&g_cnt[d[k]], 1) : 0;

    #pragma unroll
    for (int k = 0; k < 4; ++k) {
        if (k >= m) break;
        if (p[k] < CAP) {
            g_lists[d[k] * CAP + p[k]] = s[k];
        } else {
            int o = atomicAdd(&g_of_count, 1);
            if (o < MAX_OF) { g_of_src[o] = s[k]; g_of_dst[o] = d[k]; }
        }
    }
}

// ---- phase 2: gather-accumulate (+inline overflow), plain store ----------
__global__ void mp_gather_kernel(const float4* __restrict__ x,
                                 float4* __restrict__ out, int N) {
    int idx = blockIdx.x * blockDim.x + threadIdx.x;
    int node = idx >> 4;
    int q    = idx & 15;
    if (node >= N) return;

    int c = g_cnt[node];
    if (c > CAP) c = CAP;
    const int4* lst4 = (const int4*)(g_lists + node * CAP);

    float4 a0 = make_float4(0.f, 0.f, 0.f, 0.f);
    float4 a1 = make_float4(0.f, 0.f, 0.f, 0.f);
    float4 a2 = make_float4(0.f, 0.f, 0.f, 0.f);
    float4 a3 = make_float4(0.f, 0.f, 0.f, 0.f);

    int j = 0;
    // 8-wide: all 10 loads issued unconditionally before any accumulate.
    for (; j + 7 < c; j += 8) {
        int4 sA = __ldg(lst4 + (j >> 2));
        int4 sB = __ldg(lst4 + (j >> 2) + 1);
        float4 v0 = __ldg(x + sA.x * 16 + q);
        float4 v1 = __ldg(x + sA.y * 16 + q);
        float4 v2 = __ldg(x + sA.z * 16 + q);
        float4 v3 = __ldg(x + sA.w * 16 + q);
        float4 v4 = __ldg(x + sB.x * 16 + q);
        float4 v5 = __ldg(x + sB.y * 16 + q);
        float4 v6 = __ldg(x + sB.z * 16 + q);
        float4 v7 = __ldg(x + sB.w * 16 + q);
        acc_add(a0, v0); acc_add(a1, v1); acc_add(a2, v2); acc_add(a3, v3);
        acc_add(a0, v4); acc_add(a1, v5); acc_add(a2, v6); acc_add(a3, v7);
    }
    // 4-wide (round-6 proven body).
    for (; j + 3 < c; j += 4) {
        int4 s = __ldg(lst4 + (j >> 2));
        float4 v0 = __ldg(x + s.x * 16 + q);
        float4 v1 = __ldg(x + s.y * 16 + q);
        float4 v2 = __ldg(x + s.z * 16 + q);
        float4 v3 = __ldg(x + s.w * 16 + q);
        acc_add(a0, v0); acc_add(a1, v1); acc_add(a2, v2); acc_add(a3, v3);
    }
    if (j < c) {
        const int* lst = (const int*)lst4;
        for (; j < c; ++j)
            acc_add(a0, __ldg(x + __ldg(lst + j) * 16 + q));
    }

    // Fold in overflow edges targeting this node (expected: none).
    int nof = g_of_count;
    if (nof > 0) {
        if (nof > MAX_OF) nof = MAX_OF;
        for (int i = 0; i < nof; ++i)
            if (g_of_dst[i] == node)
                acc_add(a0, __ldg(x + g_of_src[i] * 16 + q));
    }

    acc_add(a0, a1); acc_add(a2, a3); acc_add(a0, a2);
    out[node * 16 + q] = a0;
}

// ---- fallback (N > N_MAX): pure atomic path ------------------------------
__global__ void mp_zero_kernel(float4* __restrict__ out, int n4) {
    int i = blockIdx.x * blockDim.x + threadIdx.x;
    if (i < n4) out[i] = make_float4(0.f, 0.f, 0.f, 0.f);
}

__global__ void mp_scatter_kernel(const float4* __restrict__ x,
                                  const int* __restrict__ ei,
                                  float* __restrict__ out, int E) {
    int idx = blockIdx.x * blockDim.x + threadIdx.x;
    int e = idx >> 4, q = idx & 15;
    if (e >= E) return;
    int src = __ldg(ei + e);
    int dst = __ldg(ei + E + e);
    float4 v = __ldg(x + src * 16 + q);
    red_add_v4(out + dst * 64 + q * 4, v);
}

extern "C" void kernel_launch(void* const* d_in, const int* in_sizes, int n_in,
                              void* d_out, int out_size) {
    const float4* x = (const float4*)d_in[0];
    const int* ei = (const int*)d_in[1];
    float* out = (float*)d_out;

    int E = in_sizes[1] / 2;          // 800000
    int N = in_sizes[0] / 64;         // 50000

    if (N <= N_MAX) {
        int rthreads = (N >> 2) + 1;
        mp_reset_kernel<<<(rthreads + 255) / 256, 256>>>(N);
        int groups = (E + 3) / 4;
        mp_fill_kernel<<<(groups + 255) / 256, 256>>>(ei, E);
        long long work = (long long)N * 16;
        mp_gather_kernel<<<(int)((work + 255) / 256), 256>>>(x, (float4*)out, N);
    } else {
        int n4 = out_size / 4;
        mp_zero_kernel<<<(n4 + 255) / 256, 256>>>((float4*)out, n4);
        long long work = (long long)E * 16;
        mp_scatter_kernel<<<(int)((work + 255) / 256), 256>>>(x, ei, out, E);
    }
}